// round 14
// baseline (speedup 1.0000x reference)
#include <cuda_runtime.h>
#include <cuda_bf16.h>
#include <math.h>
#include <stdint.h>

#define NN     50000
#define NE     600000
#define SMALL  12
#define QS     16                    // padded q/k row stride (64B aligned)
#define CAP    48                    // max in-degree incl. self loop (Poisson(12)+1)
#define INV_DK 0.2886751345948129f   // 1/sqrt(12)

typedef unsigned long long u64;

// ---------------- scratch (device globals; allocation-free) ----------------
__device__ float g_q[NN * QS];
__device__ float g_k[NN * QS];
__device__ int   g_fill[NN];
__device__ int   g_csr2[NN * CAP];
__device__ float g_w2[NN * CAP];
// A matrix [node][K=256] bf16 split hi/lo; cols 0-127 = nd, 128-255 = att.
__device__ uint2 g_Ah[NN * 64];
__device__ uint2 g_Al[NN * 64];
// B matrix [n=128][K=256] bf16 split; cols 0-127 = W1 row, 128-255 = W2 row.
__device__ __nv_bfloat16 g_Bh[128 * 256];
__device__ __nv_bfloat16 g_Bl[128 * 256];

__device__ __forceinline__ uint32_t smem_u32(const void* p) {
    uint32_t a;
    asm("{ .reg .u64 t; cvta.to.shared.u64 t, %1; cvt.u32.u64 %0, t; }" : "=r"(a) : "l"(p));
    return a;
}

#define LDSM_X4(r0,r1,r2,r3,a) \
    asm volatile("ldmatrix.sync.aligned.m8n8.x4.shared.b16 {%0,%1,%2,%3}, [%4];" \
                 : "=r"(r0),"=r"(r1),"=r"(r2),"=r"(r3) : "r"(a))

#define CP_ASYNC16(s, g) \
    asm volatile("cp.async.cg.shared.global [%0], [%1], 16;" :: "r"(s), "l"(g))
#define CP_COMMIT() asm volatile("cp.async.commit_group;" ::: "memory")
#define CP_WAIT(n)  asm volatile("cp.async.wait_group %0;" :: "n"(n) : "memory")

__device__ __forceinline__ void mma16816(float* c, const uint32_t* a, const uint32_t* b) {
    asm volatile(
        "mma.sync.aligned.m16n8k16.row.col.f32.bf16.bf16.f32 "
        "{%0,%1,%2,%3},{%4,%5,%6,%7},{%8,%9},{%0,%1,%2,%3};"
        : "+f"(c[0]), "+f"(c[1]), "+f"(c[2]), "+f"(c[3])
        : "r"(a[0]), "r"(a[1]), "r"(a[2]), "r"(a[3]), "r"(b[0]), "r"(b[1]));
}

// A frag (m16k16) at (m0,k0), row stride `st` bf16
__device__ __forceinline__ void ldAs(uint32_t* f, uint32_t sbase, int m0, int k0, int lane, int st) {
    int t = lane >> 3, r = lane & 7;
    uint32_t a = sbase + ((m0 + (t & 1) * 8 + r) * st + k0 + (t >> 1) * 8) * 2;
    LDSM_X4(f[0], f[1], f[2], f[3], a);
}
// B frags (two n8k16) at (n0,k0), row stride `st` bf16
__device__ __forceinline__ void ldBs(uint32_t* f, uint32_t sbase, int n0, int k0, int lane, int st) {
    int t = lane >> 3, r = lane & 7;
    uint32_t a = sbase + ((n0 + (t >> 1) * 8 + r) * st + k0 + (t & 1) * 8) * 2;
    LDSM_X4(f[0], f[1], f[2], f[3], a);
}

// ---------------- K1: tensor-core q/k projection + A hi/lo + W conversion ----
#define NTP       391
#define PROJ_GRID (NTP + 8)
#define WS        136                          // smem row stride (272B -> conflict-free LDSM)
#define SW_BYTES  (32 * WS * 2)                // 8704 B per W matrix
#define SA_BYTES  (128 * WS * 2)               // 34816 B per A matrix
#define DYN_PROJ  (2 * SW_BYTES + 2 * SA_BYTES)  // 87040 B

__global__ void __launch_bounds__(256, 2) k_proj(const float* __restrict__ nd,
        const float* __restrict__ Wq, const float* __restrict__ bq,
        const float* __restrict__ Wk, const float* __restrict__ bk,
        const float* __restrict__ W1, const float* __restrict__ W2) {
    extern __shared__ char dynp[];
    __shared__ float s_bias[32];

    int tid = threadIdx.x, wid = tid >> 5, lane = tid & 31;

    if (blockIdx.x >= NTP) {   // W1/W2 -> B hi/lo conversion blocks
        int bx = blockIdx.x - NTP;
        for (int i = bx * 256 + tid; i < 128 * 256; i += 8 * 256) {
            int n = i >> 8, k = i & 255;
            float w = (k < 128) ? W1[n * 128 + k] : W2[n * 128 + (k - 128)];
            __nv_bfloat16 h = __float2bfloat16(w);
            g_Bh[i] = h;
            g_Bl[i] = __float2bfloat16(w - __bfloat162float(h));
        }
        return;
    }

    unsigned short* sWh16 = (unsigned short*)dynp;
    unsigned short* sWl16 = (unsigned short*)(dynp + SW_BYTES);
    uint32_t aWh = smem_u32(dynp);
    uint32_t aWl = aWh + SW_BYTES;
    uint32_t aAh = aWh + 2 * SW_BYTES;
    uint32_t aAl = aAh + SA_BYTES;
    float* sS = (float*)dynp;                  // epilogue scoreboard aliases W

    for (int i = tid; i < 32 * WS; i += 256) { sWh16[i] = 0; sWl16[i] = 0; }
    if (tid < 24) s_bias[tid] = (tid < SMALL) ? bq[tid] : bk[tid - SMALL];
    __syncthreads();
    for (int i = tid; i < 24 * 128; i += 256) {
        int r = i >> 7, c = i & 127;
        float w = (r < SMALL) ? Wq[r * 128 + c] : Wk[(r - SMALL) * 128 + c];
        __nv_bfloat16 h = __float2bfloat16(w);
        sWh16[r * WS + c] = *(unsigned short*)&h;
        __nv_bfloat16 l = __float2bfloat16(w - __bfloat162float(h));
        sWl16[r * WS + c] = *(unsigned short*)&l;
    }

    int nb = blockIdx.x * 128;
    #pragma unroll
    for (int it = 0; it < 16; it++) {
        int idx = it * 256 + tid;
        int row = idx >> 5, l = idx & 31;
        int gm = nb + row;
        bool valid = gm < NN;
        if (!valid) gm = NN - 1;
        float4 x = ((const float4*)(nd + (size_t)gm * 128))[l];
        __nv_bfloat16 h0 = __float2bfloat16(x.x), h1 = __float2bfloat16(x.y);
        __nv_bfloat16 h2 = __float2bfloat16(x.z), h3 = __float2bfloat16(x.w);
        __nv_bfloat162 hlo = __halves2bfloat162(h0, h1);
        __nv_bfloat162 hhi = __halves2bfloat162(h2, h3);
        uint2 ph; ph.x = *(unsigned*)&hlo; ph.y = *(unsigned*)&hhi;
        __nv_bfloat162 llo = __floats2bfloat162_rn(x.x - __bfloat162float(h0),
                                                   x.y - __bfloat162float(h1));
        __nv_bfloat162 lhi = __floats2bfloat162_rn(x.z - __bfloat162float(h2),
                                                   x.w - __bfloat162float(h3));
        uint2 pl; pl.x = *(unsigned*)&llo; pl.y = *(unsigned*)&lhi;
        uint32_t doff = (uint32_t)(row * WS + l * 4) * 2;
        *(uint2*)(dynp + 2 * SW_BYTES + doff)            = ph;
        *(uint2*)(dynp + 2 * SW_BYTES + SA_BYTES + doff) = pl;
        if (valid) { g_Ah[gm * 64 + l] = ph; g_Al[gm * 64 + l] = pl; }
    }
    __syncthreads();

    float acc[4][4];
    #pragma unroll
    for (int ni = 0; ni < 4; ni++)
        #pragma unroll
        for (int e = 0; e < 4; e++) acc[ni][e] = 0.f;
    int wm = wid * 16;
    #pragma unroll
    for (int ks = 0; ks < 8; ks++) {
        int k0 = ks * 16;
        uint32_t Ah_[4], Al_[4], Bh_[2][4], Bl_[2][4];
        ldAs(Ah_, aAh, wm, k0, lane, WS);
        ldAs(Al_, aAl, wm, k0, lane, WS);
        ldBs(Bh_[0], aWh,  0, k0, lane, WS);
        ldBs(Bh_[1], aWh, 16, k0, lane, WS);
        ldBs(Bl_[0], aWl,  0, k0, lane, WS);
        ldBs(Bl_[1], aWl, 16, k0, lane, WS);
        #pragma unroll
        for (int ni = 0; ni < 4; ni++) {
            const uint32_t* bh = &Bh_[ni >> 1][(ni & 1) * 2];
            const uint32_t* bl = &Bl_[ni >> 1][(ni & 1) * 2];
            mma16816(acc[ni], Ah_, bh);
            mma16816(acc[ni], Ah_, bl);
            mma16816(acc[ni], Al_, bh);
        }
    }
    __syncthreads();

    #pragma unroll
    for (int ni = 0; ni < 4; ni++) {
        int r0 = wm + (lane >> 2);
        int cc = ni * 8 + (lane & 3) * 2;
        sS[r0 * 33 + cc]       = acc[ni][0];
        sS[r0 * 33 + cc + 1]   = acc[ni][1];
        sS[(r0 + 8) * 33 + cc]     = acc[ni][2];
        sS[(r0 + 8) * 33 + cc + 1] = acc[ni][3];
    }
    __syncthreads();

    if (tid < 128) {
        int node = nb + tid;
        if (node < NN) {
            float qv[12], kv[12], sl = 0.f;
            #pragma unroll
            for (int j = 0; j < SMALL; j++) {
                float qj = tanhf(sS[tid * 33 + j] + s_bias[j]);
                float kj = sS[tid * 33 + SMALL + j] + s_bias[SMALL + j];
                qv[j] = qj; kv[j] = kj; sl += qj * kj;
            }
            float4* q4 = (float4*)(g_q + (size_t)node * QS);
            q4[0] = make_float4(qv[0], qv[1], qv[2],  qv[3]);
            q4[1] = make_float4(qv[4], qv[5], qv[6],  qv[7]);
            q4[2] = make_float4(qv[8], qv[9], qv[10], qv[11]);
            float4* k4 = (float4*)(g_k + (size_t)node * QS);
            k4[0] = make_float4(kv[0], kv[1], kv[2],  kv[3]);
            k4[1] = make_float4(kv[4], kv[5], kv[6],  kv[7]);
            k4[2] = make_float4(kv[8], kv[9], kv[10], kv[11]);
            g_csr2[node * CAP] = node;
            g_w2[node * CAP]   = __expf(sl * INV_DK);
            g_fill[node]       = 1;
        }
    }
}

// ---------------- K2: scatter edges + per-edge weight (one atomic) ----------
__device__ __forceinline__ float dotqk(const float* __restrict__ q, const float* __restrict__ k) {
    const float4* q4 = (const float4*)q;
    const float4* k4 = (const float4*)k;
    float4 a = q4[0], b = q4[1], c = q4[2];
    float4 d = k4[0], e = k4[1], f = k4[2];
    return a.x*d.x + a.y*d.y + a.z*d.z + a.w*d.w
         + b.x*e.x + b.y*e.y + b.z*e.z + b.w*e.w
         + c.x*f.x + c.y*f.y + c.z*f.z + c.w*f.w;
}

__global__ void k_scatter(const int* __restrict__ src, const int* __restrict__ dst) {
    int e = blockIdx.x * blockDim.x + threadIdx.x;
    if (e >= NE) return;
    int s = src[e];
    int d = dst[e];
    float w = __expf(dotqk(g_q + s * QS, g_k + d * QS) * INV_DK);
    int p = atomicAdd(&g_fill[d], 1);
    g_csr2[d * CAP + p] = s;
    g_w2[d * CAP + p]   = w;
}

// ---------------- K3: weighted row-gather aggregation (sum folded in) -------
__device__ __forceinline__ void bacc(float4& acc, float w, uint2 p) {
    __nv_bfloat162 lo = *(__nv_bfloat162*)&p.x;
    __nv_bfloat162 hi = *(__nv_bfloat162*)&p.y;
    float2 f0 = __bfloat1622float2(lo);
    float2 f1 = __bfloat1622float2(hi);
    acc.x += w * f0.x; acc.y += w * f0.y;
    acc.z += w * f1.x; acc.w += w * f1.y;
}

__global__ void k_att() {
    int warp = (blockIdx.x * blockDim.x + threadIdx.x) >> 5;
    int lane = threadIdx.x & 31;
    if (warp >= NN) return;
    int deg  = g_fill[warp];
    int base = warp * CAP;

    float4 acc = make_float4(0.f, 0.f, 0.f, 0.f);
    float sw = 0.f;
    int j = 0;
    for (; j + 8 <= deg; j += 8) {
        int ss[8]; float ww[8]; uint2 xx[8];
        #pragma unroll
        for (int u = 0; u < 8; u++) { ss[u] = g_csr2[base+j+u]; ww[u] = g_w2[base+j+u]; }
        #pragma unroll
        for (int u = 0; u < 8; u++) xx[u] = g_Ah[ss[u] * 64 + lane];
        #pragma unroll
        for (int u = 0; u < 8; u++) { bacc(acc, ww[u], xx[u]); sw += ww[u]; }
    }
    for (; j + 4 <= deg; j += 4) {
        int ss[4]; float ww[4]; uint2 xx[4];
        #pragma unroll
        for (int u = 0; u < 4; u++) { ss[u] = g_csr2[base+j+u]; ww[u] = g_w2[base+j+u]; }
        #pragma unroll
        for (int u = 0; u < 4; u++) xx[u] = g_Ah[ss[u] * 64 + lane];
        #pragma unroll
        for (int u = 0; u < 4; u++) { bacc(acc, ww[u], xx[u]); sw += ww[u]; }
    }
    for (; j < deg; j++) {
        float w0 = g_w2[base+j];
        uint2 x0 = g_Ah[g_csr2[base+j] * 64 + lane];
        bacc(acc, w0, x0); sw += w0;
    }
    float invS = 1.f / sw;
    float4 r;
    r.x = acc.x * invS; r.y = acc.y * invS; r.z = acc.z * invS; r.w = acc.w * invS;

    __nv_bfloat16 h0 = __float2bfloat16(r.x), h1 = __float2bfloat16(r.y);
    __nv_bfloat16 h2 = __float2bfloat16(r.z), h3 = __float2bfloat16(r.w);
    __nv_bfloat162 hlo = __halves2bfloat162(h0, h1);
    __nv_bfloat162 hhi = __halves2bfloat162(h2, h3);
    uint2 ph; ph.x = *(unsigned*)&hlo; ph.y = *(unsigned*)&hhi;
    g_Ah[warp * 64 + 32 + lane] = ph;
    __nv_bfloat162 llo = __floats2bfloat162_rn(r.x - __bfloat162float(h0),
                                               r.y - __bfloat162float(h1));
    __nv_bfloat162 lhi = __floats2bfloat162_rn(r.z - __bfloat162float(h2),
                                               r.w - __bfloat162float(h3));
    uint2 pl; pl.x = *(unsigned*)&llo; pl.y = *(unsigned*)&lhi;
    g_Al[warp * 64 + 32 + lane] = pl;
}

// ---------------- K4: PERSISTENT B-resident GEMM, pipelined fragments --------
#define B_STRIDE  264
#define B_MAT_B   (128 * B_STRIDE * 2)
#define A_MAT_B   (128 * 72 * 2)
#define ABUF_B    (2 * A_MAT_B)
#define DYN_SMEM  (2 * B_MAT_B + 2 * ABUF_B)
#define NT        391
#define GRID_OUT  148

__global__ void __launch_bounds__(256, 1) k_out(const float* __restrict__ b2,
                                                float* __restrict__ out) {
    extern __shared__ char dyn[];
    __shared__ float s_b2[128];

    const int tid  = threadIdx.x;
    const int wid  = tid >> 5;
    const int lane = tid & 31;
    const int wm   = (wid & 1) * 64;
    const int wn   = (wid >> 1) * 32;

    if (tid < 128) s_b2[tid] = b2[tid];

    uint32_t sbase0 = smem_u32(dyn);
    uint32_t sBh = sbase0;
    uint32_t sBl = sBh + B_MAT_B;
    uint32_t aBase = sBl + B_MAT_B;
    float* sD = (float*)(dyn + 2 * B_MAT_B);

    const char* Ah8 = (const char*)g_Ah;
    const char* Al8 = (const char*)g_Al;
    const char* Bh8 = (const char*)g_Bh;
    const char* Bl8 = (const char*)g_Bl;

    #pragma unroll
    for (int it = 0; it < 16; it++) {
        int idx = it * 256 + tid;
        int row = idx >> 5, sec = idx & 31;
        uint32_t doff = (uint32_t)row * (B_STRIDE * 2) + sec * 16;
        size_t   soff = (size_t)row * 512 + sec * 16;
        CP_ASYNC16(sBh + doff, Bh8 + soff);
        CP_ASYNC16(sBl + doff, Bl8 + soff);
    }
    CP_COMMIT();

    const int srow = tid >> 3, ssec = tid & 7;
    auto stageA = [&](int t, int c, int b) {
        uint32_t base = aBase + b * ABUF_B;
        int nb = t * 128;
        #pragma unroll
        for (int it = 0; it < 4; it++) {
            int row = srow + it * 32;
            int gm = nb + row; if (gm >= NN) gm = NN - 1;
            uint32_t doff = (uint32_t)(row * 72 + ssec * 8) * 2;
            size_t aoff = ((size_t)gm * 32 + c * 8 + ssec) * 16;
            CP_ASYNC16(base + 0 * A_MAT_B + doff, Ah8 + aoff);
            CP_ASYNC16(base + 1 * A_MAT_B + doff, Al8 + aoff);
        }
        CP_COMMIT();
    };

    // double-buffered fragment registers (software pipeline across ks)
    uint32_t fAh[2][4][4], fAl[2][4][4], fBh[2][2][4], fBl[2][2][4];

    for (int t = blockIdx.x; t < NT; t += GRID_OUT) {
        float acc[4][4][4];
        #pragma unroll
        for (int mi = 0; mi < 4; mi++)
            #pragma unroll
            for (int ni = 0; ni < 4; ni++)
                #pragma unroll
                for (int e = 0; e < 4; e++) acc[mi][ni][e] = 0.f;

        stageA(t, 0, 0);

        #pragma unroll 1
        for (int c = 0; c < 4; c++) {
            int b = c & 1;
            if (c < 3) stageA(t, c + 1, b ^ 1);
            if (c < 3) { CP_WAIT(1); } else { CP_WAIT(0); }
            __syncthreads();

            uint32_t sAh = aBase + b * ABUF_B;
            uint32_t sAl = sAh + A_MAT_B;

            // prologue: load ks=0 fragments
            #pragma unroll
            for (int mi = 0; mi < 4; mi++) {
                ldAs(fAh[0][mi], sAh, wm + mi * 16, 0, lane, 72);
                ldAs(fAl[0][mi], sAl, wm + mi * 16, 0, lane, 72);
            }
            ldBs(fBh[0][0], sBh, wn +  0, c * 64, lane, B_STRIDE);
            ldBs(fBh[0][1], sBh, wn + 16, c * 64, lane, B_STRIDE);
            ldBs(fBl[0][0], sBl, wn +  0, c * 64, lane, B_STRIDE);
            ldBs(fBl[0][1], sBl, wn + 16, c * 64, lane, B_STRIDE);

            #pragma unroll
            for (int ks = 0; ks < 4; ks++) {
                int p = ks & 1;
                if (ks < 3) {   // prefetch ks+1 fragments into other buffer
                    int k0  = (ks + 1) * 16;
                    int k0g = c * 64 + k0;
                    #pragma unroll
                    for (int mi = 0; mi < 4; mi++) {
                        ldAs(fAh[p ^ 1][mi], sAh, wm + mi * 16, k0, lane, 72);
                        ldAs(fAl[p ^ 1][mi], sAl, wm + mi * 16, k0, lane, 72);
                    }
                    ldBs(fBh[p ^ 1][0], sBh, wn +  0, k0g, lane, B_STRIDE);
                    ldBs(fBh[p ^ 1][1], sBh, wn + 16, k0g, lane, B_STRIDE);
                    ldBs(fBl[p ^ 1][0], sBl, wn +  0, k0g, lane, B_STRIDE);
                    ldBs(fBl[p ^ 1][1], sBl, wn + 16, k0g, lane, B_STRIDE);
                }
                #pragma unroll
                for (int mi = 0; mi < 4; mi++)
                    #pragma unroll
                    for (int ni = 0; ni < 4; ni++) {
                        const uint32_t* bh = &fBh[p][ni >> 1][(ni & 1) * 2];
                        const uint32_t* bl = &fBl[p][ni >> 1][(ni & 1) * 2];
                        mma16816(acc[mi][ni], fAh[p][mi], bh);
                        mma16816(acc[mi][ni], fAh[p][mi], bl);
                        mma16816(acc[mi][ni], fAl[p][mi], bh);
                    }
            }
            __syncthreads();
        }

        #pragma unroll
        for (int mi = 0; mi < 4; mi++)
            #pragma unroll
            for (int ni = 0; ni < 4; ni++) {
                int r0 = wm + mi * 16 + (lane >> 2);
                int cc = wn + ni * 8 + (lane & 3) * 2;
                *(float2*)&sD[r0 * 132 + cc]       = make_float2(acc[mi][ni][0], acc[mi][ni][1]);
                *(float2*)&sD[(r0 + 8) * 132 + cc] = make_float2(acc[mi][ni][2], acc[mi][ni][3]);
            }
        __syncthreads();

        {
            int r = tid >> 1;
            int h = (tid & 1) * 64;
            float vbuf[64];
            float ssq = 0.f;
            #pragma unroll
            for (int g = 0; g < 16; g++) {
                float4 v = *(const float4*)&sD[r * 132 + h + 4 * g];
                v.x += s_b2[h + 4*g+0]; v.y += s_b2[h + 4*g+1];
                v.z += s_b2[h + 4*g+2]; v.w += s_b2[h + 4*g+3];
                vbuf[4*g+0] = v.x; vbuf[4*g+1] = v.y; vbuf[4*g+2] = v.z; vbuf[4*g+3] = v.w;
                ssq += v.x*v.x + v.y*v.y + v.z*v.z + v.w*v.w;
            }
            ssq += __shfl_xor_sync(0xffffffffu, ssq, 1);
            float rn = rsqrtf(ssq);
            int node = t * 128 + r;
            if (node < NN) {
                float* op = out + (size_t)node * 128 + h;
                #pragma unroll
                for (int g = 0; g < 16; g++) {
                    float4 o;
                    o.x = fmaxf(vbuf[4*g+0] * rn, 0.f);
                    o.y = fmaxf(vbuf[4*g+1] * rn, 0.f);
                    o.z = fmaxf(vbuf[4*g+2] * rn, 0.f);
                    o.w = fmaxf(vbuf[4*g+3] * rn, 0.f);
                    *(float4*)(op + 4 * g) = o;
                }
            }
        }
        __syncthreads();
    }
}

// ---------------- launcher (4 launches; ncu capture lands on k_out) ----------
extern "C" void kernel_launch(void* const* d_in, const int* in_sizes, int n_in,
                              void* d_out, int out_size) {
    const float* nd  = (const float*)d_in[0];
    const int*   src = (const int*)  d_in[1];
    const int*   dst = (const int*)  d_in[2];
    const float* Wq  = (const float*)d_in[3];
    const float* bq  = (const float*)d_in[4];
    const float* Wk  = (const float*)d_in[5];
    const float* bk  = (const float*)d_in[6];
    const float* W1  = (const float*)d_in[7];
    const float* W2  = (const float*)d_in[8];
    const float* b2  = (const float*)d_in[9];
    float* out = (float*)d_out;

    static bool init = false;
    if (!init) {
        cudaFuncSetAttribute(k_proj, cudaFuncAttributeMaxDynamicSharedMemorySize, DYN_PROJ);
        cudaFuncSetAttribute(k_out,  cudaFuncAttributeMaxDynamicSharedMemorySize, DYN_SMEM);
        init = true;
    }

    k_proj   <<<PROJ_GRID, 256, DYN_PROJ>>>(nd, Wq, bq, Wk, bk, W1, W2);
    k_scatter<<<(NE + 255) / 256, 256>>>(src, dst);
    k_att    <<<(NN + 7) / 8, 256>>>();
    k_out    <<<GRID_OUT, 256, DYN_SMEM>>>(b2, out);
}

// round 15
// speedup vs baseline: 1.2231x; 1.2231x over previous
#include <cuda_runtime.h>
#include <cuda_fp16.h>
#include <math.h>
#include <stdint.h>

#define NN     50000
#define NE     600000
#define SMALL  12
#define QS     16                    // padded q/k row stride (64B aligned)
#define CAP    48                    // max in-degree incl. self loop (Poisson(12)+1)
#define INV_DK 0.2886751345948129f   // 1/sqrt(12)

typedef unsigned long long u64;

// ---------------- scratch (device globals; allocation-free) ----------------
__device__ float g_q[NN * QS];
__device__ float g_k[NN * QS];
__device__ int   g_fill[NN];
__device__ int   g_csr2[NN * CAP];
__device__ float g_w2[NN * CAP];
// A matrix [node][K=256] fp16; cols 0-127 = nd, 128-255 = att. uint2 = 4 fp16.
__device__ uint2 g_Ah[NN * 64];
// B matrix [n=128][K=256] fp16; cols 0-127 = W1 row, 128-255 = W2 row.
__device__ __half g_Bh[128 * 256];

__device__ __forceinline__ uint32_t smem_u32(const void* p) {
    uint32_t a;
    asm("{ .reg .u64 t; cvta.to.shared.u64 t, %1; cvt.u32.u64 %0, t; }" : "=r"(a) : "l"(p));
    return a;
}

#define LDSM_X4(r0,r1,r2,r3,a) \
    asm volatile("ldmatrix.sync.aligned.m8n8.x4.shared.b16 {%0,%1,%2,%3}, [%4];" \
                 : "=r"(r0),"=r"(r1),"=r"(r2),"=r"(r3) : "r"(a))

#define CP_ASYNC16(s, g) \
    asm volatile("cp.async.cg.shared.global [%0], [%1], 16;" :: "r"(s), "l"(g))
#define CP_COMMIT() asm volatile("cp.async.commit_group;" ::: "memory")
#define CP_WAIT(n)  asm volatile("cp.async.wait_group %0;" :: "n"(n) : "memory")

// fp16 MMA, fp32 accumulate
__device__ __forceinline__ void mma16816(float* c, const uint32_t* a, const uint32_t* b) {
    asm volatile(
        "mma.sync.aligned.m16n8k16.row.col.f32.f16.f16.f32 "
        "{%0,%1,%2,%3},{%4,%5,%6,%7},{%8,%9},{%0,%1,%2,%3};"
        : "+f"(c[0]), "+f"(c[1]), "+f"(c[2]), "+f"(c[3])
        : "r"(a[0]), "r"(a[1]), "r"(a[2]), "r"(a[3]), "r"(b[0]), "r"(b[1]));
}

// A frag (m16k16) at (m0,k0), row stride `st` fp16
__device__ __forceinline__ void ldAs(uint32_t* f, uint32_t sbase, int m0, int k0, int lane, int st) {
    int t = lane >> 3, r = lane & 7;
    uint32_t a = sbase + ((m0 + (t & 1) * 8 + r) * st + k0 + (t >> 1) * 8) * 2;
    LDSM_X4(f[0], f[1], f[2], f[3], a);
}
// B frags (two n8k16) at (n0,k0), row stride `st` fp16
__device__ __forceinline__ void ldBs(uint32_t* f, uint32_t sbase, int n0, int k0, int lane, int st) {
    int t = lane >> 3, r = lane & 7;
    uint32_t a = sbase + ((n0 + (t >> 1) * 8 + r) * st + k0 + (t & 1) * 8) * 2;
    LDSM_X4(f[0], f[1], f[2], f[3], a);
}

// ---------------- K1: tensor-core q/k projection (3-term fp16) --------------
// Per CTA: 128 nodes. S[128x32] = X[128x128] @ [Wq|Wk]^T, fp16 hi/lo split
// (error ~2^-22: scores feed exp so they stay accurate). X-hi also written
// to g_Ah (gather/GEMM source). Blocks >= NTP convert W1/W2 -> g_Bh (fp16).
#define NTP       391
#define PROJ_GRID (NTP + 8)
#define WS        136                          // smem row stride (conflict-free LDSM)
#define SW_BYTES  (32 * WS * 2)                // 8704 B per W matrix
#define SA_BYTES  (128 * WS * 2)               // 34816 B per A matrix
#define DYN_PROJ  (2 * SW_BYTES + 2 * SA_BYTES)  // 87040 B

__global__ void __launch_bounds__(256, 2) k_proj(const float* __restrict__ nd,
        const float* __restrict__ Wq, const float* __restrict__ bq,
        const float* __restrict__ Wk, const float* __restrict__ bk,
        const float* __restrict__ W1, const float* __restrict__ W2) {
    extern __shared__ char dynp[];
    __shared__ float s_bias[32];

    int tid = threadIdx.x, wid = tid >> 5, lane = tid & 31;

    if (blockIdx.x >= NTP) {   // W1/W2 -> fp16 B conversion
        int bx = blockIdx.x - NTP;
        for (int i = bx * 256 + tid; i < 128 * 256; i += 8 * 256) {
            int n = i >> 8, k = i & 255;
            float w = (k < 128) ? W1[n * 128 + k] : W2[n * 128 + (k - 128)];
            g_Bh[i] = __float2half_rn(w);
        }
        return;
    }

    unsigned short* sWh16 = (unsigned short*)dynp;
    unsigned short* sWl16 = (unsigned short*)(dynp + SW_BYTES);
    uint32_t aWh = smem_u32(dynp);
    uint32_t aWl = aWh + SW_BYTES;
    uint32_t aAh = aWh + 2 * SW_BYTES;
    uint32_t aAl = aAh + SA_BYTES;
    float* sS = (float*)dynp;                  // epilogue scoreboard aliases W

    for (int i = tid; i < 32 * WS; i += 256) { sWh16[i] = 0; sWl16[i] = 0; }
    if (tid < 24) s_bias[tid] = (tid < SMALL) ? bq[tid] : bk[tid - SMALL];
    __syncthreads();
    for (int i = tid; i < 24 * 128; i += 256) {
        int r = i >> 7, c = i & 127;
        float w = (r < SMALL) ? Wq[r * 128 + c] : Wk[(r - SMALL) * 128 + c];
        __half h = __float2half_rn(w);
        sWh16[r * WS + c] = *(unsigned short*)&h;
        __half l = __float2half_rn(w - __half2float(h));
        sWl16[r * WS + c] = *(unsigned short*)&l;
    }

    int nb = blockIdx.x * 128;
    #pragma unroll
    for (int it = 0; it < 16; it++) {
        int idx = it * 256 + tid;
        int row = idx >> 5, l = idx & 31;
        int gm = nb + row;
        bool valid = gm < NN;
        if (!valid) gm = NN - 1;
        float4 x = ((const float4*)(nd + (size_t)gm * 128))[l];
        __half h0 = __float2half_rn(x.x), h1 = __float2half_rn(x.y);
        __half h2 = __float2half_rn(x.z), h3 = __float2half_rn(x.w);
        __half2 hlo = __halves2half2(h0, h1);
        __half2 hhi = __halves2half2(h2, h3);
        uint2 ph; ph.x = *(unsigned*)&hlo; ph.y = *(unsigned*)&hhi;
        __half2 llo = __floats2half2_rn(x.x - __half2float(h0), x.y - __half2float(h1));
        __half2 lhi = __floats2half2_rn(x.z - __half2float(h2), x.w - __half2float(h3));
        uint2 pl; pl.x = *(unsigned*)&llo; pl.y = *(unsigned*)&lhi;
        uint32_t doff = (uint32_t)(row * WS + l * 4) * 2;
        *(uint2*)(dynp + 2 * SW_BYTES + doff)            = ph;
        *(uint2*)(dynp + 2 * SW_BYTES + SA_BYTES + doff) = pl;
        if (valid) g_Ah[gm * 64 + l] = ph;
    }
    __syncthreads();

    float acc[4][4];
    #pragma unroll
    for (int ni = 0; ni < 4; ni++)
        #pragma unroll
        for (int e = 0; e < 4; e++) acc[ni][e] = 0.f;
    int wm = wid * 16;
    #pragma unroll
    for (int ks = 0; ks < 8; ks++) {
        int k0 = ks * 16;
        uint32_t Ah_[4], Al_[4], Bh_[2][4], Bl_[2][4];
        ldAs(Ah_, aAh, wm, k0, lane, WS);
        ldAs(Al_, aAl, wm, k0, lane, WS);
        ldBs(Bh_[0], aWh,  0, k0, lane, WS);
        ldBs(Bh_[1], aWh, 16, k0, lane, WS);
        ldBs(Bl_[0], aWl,  0, k0, lane, WS);
        ldBs(Bl_[1], aWl, 16, k0, lane, WS);
        #pragma unroll
        for (int ni = 0; ni < 4; ni++) {
            const uint32_t* bh = &Bh_[ni >> 1][(ni & 1) * 2];
            const uint32_t* bl = &Bl_[ni >> 1][(ni & 1) * 2];
            mma16816(acc[ni], Ah_, bh);
            mma16816(acc[ni], Ah_, bl);
            mma16816(acc[ni], Al_, bh);
        }
    }
    __syncthreads();

    #pragma unroll
    for (int ni = 0; ni < 4; ni++) {
        int r0 = wm + (lane >> 2);
        int cc = ni * 8 + (lane & 3) * 2;
        sS[r0 * 33 + cc]       = acc[ni][0];
        sS[r0 * 33 + cc + 1]   = acc[ni][1];
        sS[(r0 + 8) * 33 + cc]     = acc[ni][2];
        sS[(r0 + 8) * 33 + cc + 1] = acc[ni][3];
    }
    __syncthreads();

    if (tid < 128) {
        int node = nb + tid;
        if (node < NN) {
            float qv[12], kv[12], sl = 0.f;
            #pragma unroll
            for (int j = 0; j < SMALL; j++) {
                float qj = tanhf(sS[tid * 33 + j] + s_bias[j]);
                float kj = sS[tid * 33 + SMALL + j] + s_bias[SMALL + j];
                qv[j] = qj; kv[j] = kj; sl += qj * kj;
            }
            float4* q4 = (float4*)(g_q + (size_t)node * QS);
            q4[0] = make_float4(qv[0], qv[1], qv[2],  qv[3]);
            q4[1] = make_float4(qv[4], qv[5], qv[6],  qv[7]);
            q4[2] = make_float4(qv[8], qv[9], qv[10], qv[11]);
            float4* k4 = (float4*)(g_k + (size_t)node * QS);
            k4[0] = make_float4(kv[0], kv[1], kv[2],  kv[3]);
            k4[1] = make_float4(kv[4], kv[5], kv[6],  kv[7]);
            k4[2] = make_float4(kv[8], kv[9], kv[10], kv[11]);
            g_csr2[node * CAP] = node;
            g_w2[node * CAP]   = __expf(sl * INV_DK);
            g_fill[node]       = 1;
        }
    }
}

// ---------------- K2: scatter edges + per-edge weight (one atomic) ----------
__device__ __forceinline__ float dotqk(const float* __restrict__ q, const float* __restrict__ k) {
    const float4* q4 = (const float4*)q;
    const float4* k4 = (const float4*)k;
    float4 a = q4[0], b = q4[1], c = q4[2];
    float4 d = k4[0], e = k4[1], f = k4[2];
    return a.x*d.x + a.y*d.y + a.z*d.z + a.w*d.w
         + b.x*e.x + b.y*e.y + b.z*e.z + b.w*e.w
         + c.x*f.x + c.y*f.y + c.z*f.z + c.w*f.w;
}

__global__ void k_scatter(const int* __restrict__ src, const int* __restrict__ dst) {
    int e = blockIdx.x * blockDim.x + threadIdx.x;
    if (e >= NE) return;
    int s = src[e];
    int d = dst[e];
    float w = __expf(dotqk(g_q + s * QS, g_k + d * QS) * INV_DK);
    int p = atomicAdd(&g_fill[d], 1);
    g_csr2[d * CAP + p] = s;
    g_w2[d * CAP + p]   = w;
}

// ---------------- K3: weighted row-gather aggregation (fp16 rows) -----------
__device__ __forceinline__ void hacc(float4& acc, float w, uint2 p) {
    __half2 lo = *(__half2*)&p.x;
    __half2 hi = *(__half2*)&p.y;
    float2 f0 = __half22float2(lo);
    float2 f1 = __half22float2(hi);
    acc.x += w * f0.x; acc.y += w * f0.y;
    acc.z += w * f1.x; acc.w += w * f1.y;
}

__global__ void k_att() {
    int warp = (blockIdx.x * blockDim.x + threadIdx.x) >> 5;
    int lane = threadIdx.x & 31;
    if (warp >= NN) return;
    int deg  = g_fill[warp];
    int base = warp * CAP;

    float4 acc = make_float4(0.f, 0.f, 0.f, 0.f);
    float sw = 0.f;
    int j = 0;
    for (; j + 8 <= deg; j += 8) {
        int ss[8]; float ww[8]; uint2 xx[8];
        #pragma unroll
        for (int u = 0; u < 8; u++) { ss[u] = g_csr2[base+j+u]; ww[u] = g_w2[base+j+u]; }
        #pragma unroll
        for (int u = 0; u < 8; u++) xx[u] = g_Ah[ss[u] * 64 + lane];
        #pragma unroll
        for (int u = 0; u < 8; u++) { hacc(acc, ww[u], xx[u]); sw += ww[u]; }
    }
    for (; j + 4 <= deg; j += 4) {
        int ss[4]; float ww[4]; uint2 xx[4];
        #pragma unroll
        for (int u = 0; u < 4; u++) { ss[u] = g_csr2[base+j+u]; ww[u] = g_w2[base+j+u]; }
        #pragma unroll
        for (int u = 0; u < 4; u++) xx[u] = g_Ah[ss[u] * 64 + lane];
        #pragma unroll
        for (int u = 0; u < 4; u++) { hacc(acc, ww[u], xx[u]); sw += ww[u]; }
    }
    for (; j < deg; j++) {
        float w0 = g_w2[base+j];
        uint2 x0 = g_Ah[g_csr2[base+j] * 64 + lane];
        hacc(acc, w0, x0); sw += w0;
    }
    float invS = 1.f / sw;
    float4 r;
    r.x = acc.x * invS; r.y = acc.y * invS; r.z = acc.z * invS; r.w = acc.w * invS;

    // write att as fp16 into A cols 128-255 (uint2 slots 32+lane)
    __half2 hlo = __floats2half2_rn(r.x, r.y);
    __half2 hhi = __floats2half2_rn(r.z, r.w);
    uint2 ph; ph.x = *(unsigned*)&hlo; ph.y = *(unsigned*)&hhi;
    g_Ah[warp * 64 + 32 + lane] = ph;
}

// ---------------- K4: persistent B-resident SINGLE-TERM fp16 GEMM -----------
// 296 CTAs (2/SM). Each CTA stages B (fp16, 67.5KB) once; A chunks (18.4KB)
// double-buffered. 1/3 the MMAs of the 3-term bf16 scheme.
#define B_STRIDE  264
#define B_MAT_B   (128 * B_STRIDE * 2)         // 67584
#define A_MAT_B   (128 * 72 * 2)               // 18432
#define DYN_SMEM  (B_MAT_B + 2 * A_MAT_B)      // 104448 -> 2 CTAs/SM
#define NT        391
#define GRID_OUT  296

__global__ void __launch_bounds__(256, 2) k_out(const float* __restrict__ b2,
                                                float* __restrict__ out) {
    extern __shared__ char dyn[];
    __shared__ float s_b2[128];

    const int tid  = threadIdx.x;
    const int wid  = tid >> 5;
    const int lane = tid & 31;
    const int wmh  = wid & 1;                  // 0/1 -> M half
    const int wm   = wmh * 64;
    const int wn   = (wid >> 1) * 32;

    if (tid < 128) s_b2[tid] = b2[tid];

    uint32_t sbase0 = smem_u32(dyn);
    uint32_t sBh = sbase0;
    uint32_t aBase = sBh + B_MAT_B;
    float* sD = (float*)(dyn + B_MAT_B);       // epilogue scratch [64][132] (33.8KB <= 36.9KB)

    const char* Ah8 = (const char*)g_Ah;
    const char* Bh8 = (const char*)g_Bh;

    // stage resident B (fp16): 128 rows x 32 sectors(16B)
    #pragma unroll
    for (int it = 0; it < 16; it++) {
        int idx = it * 256 + tid;
        int row = idx >> 5, sec = idx & 31;
        CP_ASYNC16(sBh + (uint32_t)row * (B_STRIDE * 2) + sec * 16,
                   Bh8 + (size_t)row * 512 + sec * 16);
    }
    CP_COMMIT();

    const int srow = tid >> 3, ssec = tid & 7;
    auto stageA = [&](int t, int c, int b) {
        uint32_t base = aBase + b * A_MAT_B;
        int nb = t * 128;
        #pragma unroll
        for (int it = 0; it < 4; it++) {
            int row = srow + it * 32;
            int gm = nb + row; if (gm >= NN) gm = NN - 1;
            CP_ASYNC16(base + (uint32_t)(row * 72 + ssec * 8) * 2,
                       Ah8 + ((size_t)gm * 32 + c * 8 + ssec) * 16);
        }
        CP_COMMIT();
    };

    for (int t = blockIdx.x; t < NT; t += GRID_OUT) {
        float acc[4][4][4];
        #pragma unroll
        for (int mi = 0; mi < 4; mi++)
            #pragma unroll
            for (int ni = 0; ni < 4; ni++)
                #pragma unroll
                for (int e = 0; e < 4; e++) acc[mi][ni][e] = 0.f;

        stageA(t, 0, 0);

        #pragma unroll 1
        for (int c = 0; c < 4; c++) {
            int b = c & 1;
            if (c < 3) stageA(t, c + 1, b ^ 1);
            if (c < 3) { CP_WAIT(1); } else { CP_WAIT(0); }
            __syncthreads();

            uint32_t sAh = aBase + b * A_MAT_B;

            #pragma unroll
            for (int ks = 0; ks < 4; ks++) {
                int k0  = ks * 16;
                int k0g = c * 64 + k0;
                uint32_t Ah_[4][4], Bh_[2][4];
                #pragma unroll
                for (int mi = 0; mi < 4; mi++)
                    ldAs(Ah_[mi], sAh, wm + mi * 16, k0, lane, 72);
                ldBs(Bh_[0], sBh, wn +  0, k0g, lane, B_STRIDE);
                ldBs(Bh_[1], sBh, wn + 16, k0g, lane, B_STRIDE);
                #pragma unroll
                for (int mi = 0; mi < 4; mi++)
                    #pragma unroll
                    for (int ni = 0; ni < 4; ni++)
                        mma16816(acc[mi][ni], Ah_[mi],
                                 &Bh_[ni >> 1][(ni & 1) * 2]);
            }
            __syncthreads();
        }

        // epilogue in two 64-row passes (sD only spans the A-buffer region)
        #pragma unroll 1
        for (int p = 0; p < 2; p++) {
            if (wmh == p) {
                #pragma unroll
                for (int mi = 0; mi < 4; mi++)
                    #pragma unroll
                    for (int ni = 0; ni < 4; ni++) {
                        int r0 = mi * 16 + (lane >> 2);       // local 0..63
                        int cc = wn + ni * 8 + (lane & 3) * 2;
                        *(float2*)&sD[r0 * 132 + cc]       = make_float2(acc[mi][ni][0], acc[mi][ni][1]);
                        *(float2*)&sD[(r0 + 8) * 132 + cc] = make_float2(acc[mi][ni][2], acc[mi][ni][3]);
                    }
            }
            __syncthreads();
            {
                int r = tid >> 2;                  // 0..63 local row
                int h = (tid & 3) * 32;
                float vbuf[32];
                float ssq = 0.f;
                #pragma unroll
                for (int g = 0; g < 8; g++) {
                    float4 v = *(const float4*)&sD[r * 132 + h + 4 * g];
                    v.x += s_b2[h + 4*g+0]; v.y += s_b2[h + 4*g+1];
                    v.z += s_b2[h + 4*g+2]; v.w += s_b2[h + 4*g+3];
                    vbuf[4*g+0] = v.x; vbuf[4*g+1] = v.y; vbuf[4*g+2] = v.z; vbuf[4*g+3] = v.w;
                    ssq += v.x*v.x + v.y*v.y + v.z*v.z + v.w*v.w;
                }
                ssq += __shfl_xor_sync(0xffffffffu, ssq, 1, 4);
                ssq += __shfl_xor_sync(0xffffffffu, ssq, 2, 4);
                float rn = rsqrtf(ssq);
                int node = t * 128 + p * 64 + r;
                if (node < NN) {
                    float* op = out + (size_t)node * 128 + h;
                    #pragma unroll
                    for (int g = 0; g < 8; g++) {
                        float4 o;
                        o.x = fmaxf(vbuf[4*g+0] * rn, 0.f);
                        o.y = fmaxf(vbuf[4*g+1] * rn, 0.f);
                        o.z = fmaxf(vbuf[4*g+2] * rn, 0.f);
                        o.w = fmaxf(vbuf[4*g+3] * rn, 0.f);
                        *(float4*)(op + 4 * g) = o;
                    }
                }
            }
            __syncthreads();
        }
    }
}

// ---------------- launcher (4 launches; ncu capture lands on k_out) ----------
extern "C" void kernel_launch(void* const* d_in, const int* in_sizes, int n_in,
                              void* d_out, int out_size) {
    const float* nd  = (const float*)d_in[0];
    const int*   src = (const int*)  d_in[1];
    const int*   dst = (const int*)  d_in[2];
    const float* Wq  = (const float*)d_in[3];
    const float* bq  = (const float*)d_in[4];
    const float* Wk  = (const float*)d_in[5];
    const float* bk  = (const float*)d_in[6];
    const float* W1  = (const float*)d_in[7];
    const float* W2  = (const float*)d_in[8];
    const float* b2  = (const float*)d_in[9];
    float* out = (float*)d_out;

    static bool init = false;
    if (!init) {
        cudaFuncSetAttribute(k_proj, cudaFuncAttributeMaxDynamicSharedMemorySize, DYN_PROJ);
        cudaFuncSetAttribute(k_out,  cudaFuncAttributeMaxDynamicSharedMemorySize, DYN_SMEM);
        init = true;
    }

    k_proj   <<<PROJ_GRID, 256, DYN_PROJ>>>(nd, Wq, bq, Wk, bk, W1, W2);
    k_scatter<<<(NE + 255) / 256, 256>>>(src, dst);
    k_att    <<<(NN + 7) / 8, 256>>>();
    k_out    <<<GRID_OUT, 256, DYN_SMEM>>>(b2, out);
}

// round 16
// speedup vs baseline: 1.3109x; 1.0718x over previous
#include <cuda_runtime.h>
#include <cuda_fp16.h>
#include <math.h>
#include <stdint.h>

#define NN     50000
#define NE     600000
#define SMALL  12
#define QS     16                    // padded q/k row stride (64B aligned)
#define CAP    48                    // max in-degree incl. self loop (Poisson(12)+1)
#define INV_DK 0.2886751345948129f   // 1/sqrt(12)

typedef unsigned long long u64;

// ---------------- scratch (device globals; allocation-free) ----------------
__device__ float g_q[NN * QS];
__device__ float g_k[NN * QS];
__device__ int   g_fill[NN];
__device__ int2  g_ew[NN * CAP];     // per-edge {src, weight bits}
// A matrix [node][K=256] fp16; cols 0-127 = nd, 128-255 = att. uint2 = 4 fp16.
__device__ uint2 g_Ah[NN * 64];
// B matrix [n=128][K=256] fp16; cols 0-127 = W1 row, 128-255 = W2 row.
__device__ __half g_Bh[128 * 256];

__device__ __forceinline__ uint32_t smem_u32(const void* p) {
    uint32_t a;
    asm("{ .reg .u64 t; cvta.to.shared.u64 t, %1; cvt.u32.u64 %0, t; }" : "=r"(a) : "l"(p));
    return a;
}
__device__ __forceinline__ u64 pack2(float lo, float hi) {
    u64 r; asm("mov.b64 %0, {%1, %2};" : "=l"(r) : "f"(lo), "f"(hi)); return r;
}
__device__ __forceinline__ void fma2(u64& d, u64 a, u64 b) {
    asm("fma.rn.f32x2 %0, %1, %2, %0;" : "+l"(d) : "l"(a), "l"(b));
}
__device__ __forceinline__ float2 unpk2(u64 v) {
    float lo, hi; asm("mov.b64 {%0, %1}, %2;" : "=f"(lo), "=f"(hi) : "l"(v));
    return make_float2(lo, hi);
}

#define LDSM_X4(r0,r1,r2,r3,a) \
    asm volatile("ldmatrix.sync.aligned.m8n8.x4.shared.b16 {%0,%1,%2,%3}, [%4];" \
                 : "=r"(r0),"=r"(r1),"=r"(r2),"=r"(r3) : "r"(a))

#define CP_ASYNC16(s, g) \
    asm volatile("cp.async.cg.shared.global [%0], [%1], 16;" :: "r"(s), "l"(g))
#define CP_COMMIT() asm volatile("cp.async.commit_group;" ::: "memory")
#define CP_WAIT(n)  asm volatile("cp.async.wait_group %0;" :: "n"(n) : "memory")

// fp16 MMA, fp32 accumulate
__device__ __forceinline__ void mma16816(float* c, const uint32_t* a, const uint32_t* b) {
    asm volatile(
        "mma.sync.aligned.m16n8k16.row.col.f32.f16.f16.f32 "
        "{%0,%1,%2,%3},{%4,%5,%6,%7},{%8,%9},{%0,%1,%2,%3};"
        : "+f"(c[0]), "+f"(c[1]), "+f"(c[2]), "+f"(c[3])
        : "r"(a[0]), "r"(a[1]), "r"(a[2]), "r"(a[3]), "r"(b[0]), "r"(b[1]));
}

__device__ __forceinline__ void ldAs(uint32_t* f, uint32_t sbase, int m0, int k0, int lane, int st) {
    int t = lane >> 3, r = lane & 7;
    uint32_t a = sbase + ((m0 + (t & 1) * 8 + r) * st + k0 + (t >> 1) * 8) * 2;
    LDSM_X4(f[0], f[1], f[2], f[3], a);
}
__device__ __forceinline__ void ldBs(uint32_t* f, uint32_t sbase, int n0, int k0, int lane, int st) {
    int t = lane >> 3, r = lane & 7;
    uint32_t a = sbase + ((n0 + (t >> 1) * 8 + r) * st + k0 + (t & 1) * 8) * 2;
    LDSM_X4(f[0], f[1], f[2], f[3], a);
}

// ---------------- K1: tensor-core q/k projection (3-term fp16) --------------
#define NTP       391
#define PROJ_GRID (NTP + 8)
#define WS        136
#define SW_BYTES  (32 * WS * 2)
#define SA_BYTES  (128 * WS * 2)
#define DYN_PROJ  (2 * SW_BYTES + 2 * SA_BYTES)

__global__ void __launch_bounds__(256, 2) k_proj(const float* __restrict__ nd,
        const float* __restrict__ Wq, const float* __restrict__ bq,
        const float* __restrict__ Wk, const float* __restrict__ bk,
        const float* __restrict__ W1, const float* __restrict__ W2) {
    extern __shared__ char dynp[];
    __shared__ float s_bias[32];

    int tid = threadIdx.x, wid = tid >> 5, lane = tid & 31;

    if (blockIdx.x >= NTP) {   // W1/W2 -> fp16 B conversion
        int bx = blockIdx.x - NTP;
        for (int i = bx * 256 + tid; i < 128 * 256; i += 8 * 256) {
            int n = i >> 8, k = i & 255;
            float w = (k < 128) ? W1[n * 128 + k] : W2[n * 128 + (k - 128)];
            g_Bh[i] = __float2half_rn(w);
        }
        return;
    }

    unsigned short* sWh16 = (unsigned short*)dynp;
    unsigned short* sWl16 = (unsigned short*)(dynp + SW_BYTES);
    uint32_t aWh = smem_u32(dynp);
    uint32_t aWl = aWh + SW_BYTES;
    uint32_t aAh = aWh + 2 * SW_BYTES;
    uint32_t aAl = aAh + SA_BYTES;
    float* sS = (float*)dynp;                  // epilogue scoreboard aliases W

    for (int i = tid; i < 32 * WS; i += 256) { sWh16[i] = 0; sWl16[i] = 0; }
    if (tid < 24) s_bias[tid] = (tid < SMALL) ? bq[tid] : bk[tid - SMALL];
    __syncthreads();
    for (int i = tid; i < 24 * 128; i += 256) {
        int r = i >> 7, c = i & 127;
        float w = (r < SMALL) ? Wq[r * 128 + c] : Wk[(r - SMALL) * 128 + c];
        __half h = __float2half_rn(w);
        sWh16[r * WS + c] = *(unsigned short*)&h;
        __half l = __float2half_rn(w - __half2float(h));
        sWl16[r * WS + c] = *(unsigned short*)&l;
    }

    int nb = blockIdx.x * 128;
    #pragma unroll
    for (int it = 0; it < 16; it++) {
        int idx = it * 256 + tid;
        int row = idx >> 5, l = idx & 31;
        int gm = nb + row;
        bool valid = gm < NN;
        if (!valid) gm = NN - 1;
        float4 x = ((const float4*)(nd + (size_t)gm * 128))[l];
        __half h0 = __float2half_rn(x.x), h1 = __float2half_rn(x.y);
        __half h2 = __float2half_rn(x.z), h3 = __float2half_rn(x.w);
        __half2 hlo = __halves2half2(h0, h1);
        __half2 hhi = __halves2half2(h2, h3);
        uint2 ph; ph.x = *(unsigned*)&hlo; ph.y = *(unsigned*)&hhi;
        __half2 llo = __floats2half2_rn(x.x - __half2float(h0), x.y - __half2float(h1));
        __half2 lhi = __floats2half2_rn(x.z - __half2float(h2), x.w - __half2float(h3));
        uint2 pl; pl.x = *(unsigned*)&llo; pl.y = *(unsigned*)&lhi;
        uint32_t doff = (uint32_t)(row * WS + l * 4) * 2;
        *(uint2*)(dynp + 2 * SW_BYTES + doff)            = ph;
        *(uint2*)(dynp + 2 * SW_BYTES + SA_BYTES + doff) = pl;
        if (valid) g_Ah[gm * 64 + l] = ph;
    }
    __syncthreads();

    float acc[4][4];
    #pragma unroll
    for (int ni = 0; ni < 4; ni++)
        #pragma unroll
        for (int e = 0; e < 4; e++) acc[ni][e] = 0.f;
    int wm = wid * 16;
    #pragma unroll
    for (int ks = 0; ks < 8; ks++) {
        int k0 = ks * 16;
        uint32_t Ah_[4], Al_[4], Bh_[2][4], Bl_[2][4];
        ldAs(Ah_, aAh, wm, k0, lane, WS);
        ldAs(Al_, aAl, wm, k0, lane, WS);
        ldBs(Bh_[0], aWh,  0, k0, lane, WS);
        ldBs(Bh_[1], aWh, 16, k0, lane, WS);
        ldBs(Bl_[0], aWl,  0, k0, lane, WS);
        ldBs(Bl_[1], aWl, 16, k0, lane, WS);
        #pragma unroll
        for (int ni = 0; ni < 4; ni++) {
            const uint32_t* bh = &Bh_[ni >> 1][(ni & 1) * 2];
            const uint32_t* bl = &Bl_[ni >> 1][(ni & 1) * 2];
            mma16816(acc[ni], Ah_, bh);
            mma16816(acc[ni], Ah_, bl);
            mma16816(acc[ni], Al_, bh);
        }
    }
    __syncthreads();

    #pragma unroll
    for (int ni = 0; ni < 4; ni++) {
        int r0 = wm + (lane >> 2);
        int cc = ni * 8 + (lane & 3) * 2;
        sS[r0 * 33 + cc]       = acc[ni][0];
        sS[r0 * 33 + cc + 1]   = acc[ni][1];
        sS[(r0 + 8) * 33 + cc]     = acc[ni][2];
        sS[(r0 + 8) * 33 + cc + 1] = acc[ni][3];
    }
    __syncthreads();

    if (tid < 128) {
        int node = nb + tid;
        if (node < NN) {
            float qv[12], kv[12], sl = 0.f;
            #pragma unroll
            for (int j = 0; j < SMALL; j++) {
                float qj = tanhf(sS[tid * 33 + j] + s_bias[j]);
                float kj = sS[tid * 33 + SMALL + j] + s_bias[SMALL + j];
                qv[j] = qj; kv[j] = kj; sl += qj * kj;
            }
            float4* q4 = (float4*)(g_q + (size_t)node * QS);
            q4[0] = make_float4(qv[0], qv[1], qv[2],  qv[3]);
            q4[1] = make_float4(qv[4], qv[5], qv[6],  qv[7]);
            q4[2] = make_float4(qv[8], qv[9], qv[10], qv[11]);
            float4* k4 = (float4*)(g_k + (size_t)node * QS);
            k4[0] = make_float4(kv[0], kv[1], kv[2],  kv[3]);
            k4[1] = make_float4(kv[4], kv[5], kv[6],  kv[7]);
            k4[2] = make_float4(kv[8], kv[9], kv[10], kv[11]);
            g_ew[node * CAP] = make_int2(node, __float_as_int(__expf(sl * INV_DK)));
            g_fill[node]     = 1;
        }
    }
}

// ---------------- K2: scatter edges + per-edge weight (one int2 store) ------
__device__ __forceinline__ float dotqk(const float* __restrict__ q, const float* __restrict__ k) {
    const float4* q4 = (const float4*)q;
    const float4* k4 = (const float4*)k;
    float4 a = q4[0], b = q4[1], c = q4[2];
    float4 d = k4[0], e = k4[1], f = k4[2];
    return a.x*d.x + a.y*d.y + a.z*d.z + a.w*d.w
         + b.x*e.x + b.y*e.y + b.z*e.z + b.w*e.w
         + c.x*f.x + c.y*f.y + c.z*f.z + c.w*f.w;
}

__global__ void k_scatter(const int* __restrict__ src, const int* __restrict__ dst) {
    int e = blockIdx.x * blockDim.x + threadIdx.x;
    if (e >= NE) return;
    int s = src[e];
    int d = dst[e];
    float w = __expf(dotqk(g_q + s * QS, g_k + d * QS) * INV_DK);
    int p = atomicAdd(&g_fill[d], 1);
    g_ew[d * CAP + p] = make_int2(s, __float_as_int(w));
}

// ---------------- K3: weighted row-gather aggregation (f32x2 FMA) -----------
__device__ __forceinline__ void hacc2(u64& a01, u64& a23, u64 wpk, uint2 p) {
    float2 f0 = __half22float2(*(__half2*)&p.x);
    float2 f1 = __half22float2(*(__half2*)&p.y);
    fma2(a01, wpk, pack2(f0.x, f0.y));
    fma2(a23, wpk, pack2(f1.x, f1.y));
}

__global__ void k_att() {
    int warp = (blockIdx.x * blockDim.x + threadIdx.x) >> 5;
    int lane = threadIdx.x & 31;
    if (warp >= NN) return;
    int deg  = g_fill[warp];
    int base = warp * CAP;

    u64 a01 = 0, a23 = 0;
    float sw = 0.f;
    int j = 0;
    for (; j + 8 <= deg; j += 8) {
        int2 ew[8]; uint2 xx[8];
        #pragma unroll
        for (int u = 0; u < 8; u++) ew[u] = g_ew[base + j + u];
        #pragma unroll
        for (int u = 0; u < 8; u++) xx[u] = g_Ah[ew[u].x * 64 + lane];
        #pragma unroll
        for (int u = 0; u < 8; u++) {
            float w = __int_as_float(ew[u].y);
            hacc2(a01, a23, pack2(w, w), xx[u]);
            sw += w;
        }
    }
    for (; j + 4 <= deg; j += 4) {
        int2 ew[4]; uint2 xx[4];
        #pragma unroll
        for (int u = 0; u < 4; u++) ew[u] = g_ew[base + j + u];
        #pragma unroll
        for (int u = 0; u < 4; u++) xx[u] = g_Ah[ew[u].x * 64 + lane];
        #pragma unroll
        for (int u = 0; u < 4; u++) {
            float w = __int_as_float(ew[u].y);
            hacc2(a01, a23, pack2(w, w), xx[u]);
            sw += w;
        }
    }
    for (; j < deg; j++) {
        int2 ew = g_ew[base + j];
        uint2 x0 = g_Ah[ew.x * 64 + lane];
        float w = __int_as_float(ew.y);
        hacc2(a01, a23, pack2(w, w), x0);
        sw += w;
    }
    float invS = 1.f / sw;
    float2 r01 = unpk2(a01), r23 = unpk2(a23);

    __half2 hlo = __floats2half2_rn(r01.x * invS, r01.y * invS);
    __half2 hhi = __floats2half2_rn(r23.x * invS, r23.y * invS);
    uint2 ph; ph.x = *(unsigned*)&hlo; ph.y = *(unsigned*)&hhi;
    g_Ah[warp * 64 + 32 + lane] = ph;
}

// ---------------- K4: persistent B-resident fp16 GEMM, register epilogue ----
#define B_STRIDE  264
#define B_MAT_B   (128 * B_STRIDE * 2)         // 67584
#define A_MAT_B   (128 * 72 * 2)               // 18432
#define DYN_SMEM  (B_MAT_B + 2 * A_MAT_B)      // 104448 -> 2 CTAs/SM
#define NT        391
#define GRID_OUT  296

__global__ void __launch_bounds__(256, 2) k_out(const float* __restrict__ b2,
                                                float* __restrict__ out) {
    extern __shared__ char dyn[];
    __shared__ float s_b2[128];
    __shared__ float s_ssq[128];

    const int tid  = threadIdx.x;
    const int wid  = tid >> 5;
    const int lane = tid & 31;
    const int wm   = (wid & 1) * 64;
    const int wn   = (wid >> 1) * 32;

    if (tid < 128) s_b2[tid] = b2[tid];

    uint32_t sbase0 = smem_u32(dyn);
    uint32_t sBh = sbase0;
    uint32_t aBase = sBh + B_MAT_B;

    const char* Ah8 = (const char*)g_Ah;
    const char* Bh8 = (const char*)g_Bh;

    // stage resident B (fp16): 128 rows x 32 sectors(16B)
    #pragma unroll
    for (int it = 0; it < 16; it++) {
        int idx = it * 256 + tid;
        int row = idx >> 5, sec = idx & 31;
        CP_ASYNC16(sBh + (uint32_t)row * (B_STRIDE * 2) + sec * 16,
                   Bh8 + (size_t)row * 512 + sec * 16);
    }
    CP_COMMIT();
    __syncthreads();   // s_b2 visible before acc init below

    const int srow = tid >> 3, ssec = tid & 7;
    auto stageA = [&](int t, int c, int b) {
        uint32_t base = aBase + b * A_MAT_B;
        int nb = t * 128;
        #pragma unroll
        for (int it = 0; it < 4; it++) {
            int row = srow + it * 32;
            int gm = nb + row; if (gm >= NN) gm = NN - 1;
            CP_ASYNC16(base + (uint32_t)(row * 72 + ssec * 8) * 2,
                       Ah8 + ((size_t)gm * 32 + c * 8 + ssec) * 16);
        }
        CP_COMMIT();
    };

    stageA(blockIdx.x, 0, 0);

    // bias values for this thread's columns (reused across tiles)
    float bc0[4], bc1[4];
    #pragma unroll
    for (int ni = 0; ni < 4; ni++) {
        int cc = wn + ni * 8 + (lane & 3) * 2;
        bc0[ni] = s_b2[cc]; bc1[ni] = s_b2[cc + 1];
    }

    for (int t = blockIdx.x; t < NT; t += GRID_OUT) {
        float acc[4][4][4];
        #pragma unroll
        for (int mi = 0; mi < 4; mi++)
            #pragma unroll
            for (int ni = 0; ni < 4; ni++) {
                acc[mi][ni][0] = bc0[ni]; acc[mi][ni][1] = bc1[ni];
                acc[mi][ni][2] = bc0[ni]; acc[mi][ni][3] = bc1[ni];
            }

        #pragma unroll 1
        for (int c = 0; c < 4; c++) {
            int b = c & 1;
            if (c < 3) {
                stageA(t, c + 1, b ^ 1);
                CP_WAIT(1);
            } else {
                int nt = t + GRID_OUT;
                if (nt < NT) { stageA(nt, 0, b ^ 1); CP_WAIT(1); }
                else         { CP_WAIT(0); }
            }
            __syncthreads();

            uint32_t sAh = aBase + b * A_MAT_B;

            #pragma unroll
            for (int ks = 0; ks < 4; ks++) {
                int k0  = ks * 16;
                int k0g = c * 64 + k0;
                uint32_t Ah_[4][4], Bh_[2][4];
                #pragma unroll
                for (int mi = 0; mi < 4; mi++)
                    ldAs(Ah_[mi], sAh, wm + mi * 16, k0, lane, 72);
                ldBs(Bh_[0], sBh, wn +  0, k0g, lane, B_STRIDE);
                ldBs(Bh_[1], sBh, wn + 16, k0g, lane, B_STRIDE);
                #pragma unroll
                for (int mi = 0; mi < 4; mi++)
                    #pragma unroll
                    for (int ni = 0; ni < 4; ni++)
                        mma16816(acc[mi][ni], Ah_[mi],
                                 &Bh_[ni >> 1][(ni & 1) * 2]);
            }
            __syncthreads();
        }

        // ---- register epilogue: ssq via shfl + smem atomics, direct stores --
        if (tid < 128) s_ssq[tid] = 0.f;
        __syncthreads();
        #pragma unroll
        for (int mi = 0; mi < 4; mi++) {
            float p0 = 0.f, p1 = 0.f;
            #pragma unroll
            for (int ni = 0; ni < 4; ni++) {
                p0 += acc[mi][ni][0] * acc[mi][ni][0] + acc[mi][ni][1] * acc[mi][ni][1];
                p1 += acc[mi][ni][2] * acc[mi][ni][2] + acc[mi][ni][3] * acc[mi][ni][3];
            }
            p0 += __shfl_xor_sync(0xffffffffu, p0, 1, 4);
            p0 += __shfl_xor_sync(0xffffffffu, p0, 2, 4);
            p1 += __shfl_xor_sync(0xffffffffu, p1, 1, 4);
            p1 += __shfl_xor_sync(0xffffffffu, p1, 2, 4);
            if ((lane & 3) == 0) {
                int r0 = wm + mi * 16 + (lane >> 2);
                atomicAdd(&s_ssq[r0], p0);
                atomicAdd(&s_ssq[r0 + 8], p1);
            }
        }
        __syncthreads();
        {
            int nb = t * 128;
            #pragma unroll
            for (int mi = 0; mi < 4; mi++) {
                int r0 = wm + mi * 16 + (lane >> 2);
                float rn0 = rsqrtf(s_ssq[r0]);
                float rn1 = rsqrtf(s_ssq[r0 + 8]);
                int n0 = nb + r0;
                #pragma unroll
                for (int ni = 0; ni < 4; ni++) {
                    int cc = wn + ni * 8 + (lane & 3) * 2;
                    if (n0 < NN) {
                        float2 o;
                        o.x = fmaxf(acc[mi][ni][0] * rn0, 0.f);
                        o.y = fmaxf(acc[mi][ni][1] * rn0, 0.f);
                        *(float2*)(out + (size_t)n0 * 128 + cc) = o;
                    }
                    if (n0 + 8 < NN) {
                        float2 o;
                        o.x = fmaxf(acc[mi][ni][2] * rn1, 0.f);
                        o.y = fmaxf(acc[mi][ni][3] * rn1, 0.f);
                        *(float2*)(out + (size_t)(n0 + 8) * 128 + cc) = o;
                    }
                }
            }
        }
        __syncthreads();   // s_ssq reads done before next tile zeroes it
    }
}

// ---------------- launcher (4 launches; ncu capture lands on k_out) ----------
extern "C" void kernel_launch(void* const* d_in, const int* in_sizes, int n_in,
                              void* d_out, int out_size) {
    const float* nd  = (const float*)d_in[0];
    const int*   src = (const int*)  d_in[1];
    const int*   dst = (const int*)  d_in[2];
    const float* Wq  = (const float*)d_in[3];
    const float* bq  = (const float*)d_in[4];
    const float* Wk  = (const float*)d_in[5];
    const float* bk  = (const float*)d_in[6];
    const float* W1  = (const float*)d_in[7];
    const float* W2  = (const float*)d_in[8];
    const float* b2  = (const float*)d_in[9];
    float* out = (float*)d_out;

    static bool init = false;
    if (!init) {
        cudaFuncSetAttribute(k_proj, cudaFuncAttributeMaxDynamicSharedMemorySize, DYN_PROJ);
        cudaFuncSetAttribute(k_out,  cudaFuncAttributeMaxDynamicSharedMemorySize, DYN_SMEM);
        init = true;
    }

    k_proj   <<<PROJ_GRID, 256, DYN_PROJ>>>(nd, Wq, bq, Wk, bk, W1, W2);
    k_scatter<<<(NE + 255) / 256, 256>>>(src, dst);
    k_att    <<<(NN + 7) / 8, 256>>>();
    k_out    <<<GRID_OUT, 256, DYN_SMEM>>>(b2, out);
}